// round 14
// baseline (speedup 1.0000x reference)
#include <cuda_runtime.h>
#include <cuda_fp16.h>
#include <math.h>
#include <stdint.h>

#define K_DIM   2048
#define N_DIM   160
#define NC      10
#define DC      16
#define BM      64
#define BK      64
#define NCHUNK  (K_DIM / BK)          // 32
#define NTHREAD 128
#define HAT_STRIDE 165

// fp16 tiles, row stride 144B -> conflict-free ldmatrix
#define ROWB    144
#define A_STAGE (64 * ROWB)               // 9216
#define B_BASE  (2 * A_STAGE)             // 18432
#define B_STAGE (160 * ROWB)              // 23040
#define SMEM_TOTAL (B_BASE + 2 * B_STAGE) // 64512 ; hat 42240 fits; 2 CTAs ~126KB

// Precomputed transposed fp16 weights: Wt[n][k] = fp16(W[k][n])
__device__ __half g_Wt_h[N_DIM * K_DIM];

// ---------------- helpers ----------------
__device__ __forceinline__ uint32_t smem_u32(const void* p) {
    uint32_t a;
    asm("{ .reg .u64 t; cvta.to.shared.u64 t, %1; cvt.u32.u64 %0, t; }" : "=r"(a) : "l"(p));
    return a;
}
__device__ __forceinline__ void ldsm4(uint32_t* d, uint32_t addr) {
    asm volatile("ldmatrix.sync.aligned.m8n8.x4.shared.b16 {%0,%1,%2,%3}, [%4];"
                 : "=r"(d[0]), "=r"(d[1]), "=r"(d[2]), "=r"(d[3]) : "r"(addr));
}
__device__ __forceinline__ void mma16816(float* c, const uint32_t* a,
                                         uint32_t b0, uint32_t b1) {
    asm volatile("mma.sync.aligned.m16n8k16.row.col.f32.f16.f16.f32 "
                 "{%0,%1,%2,%3}, {%4,%5,%6,%7}, {%8,%9}, {%0,%1,%2,%3};"
                 : "+f"(c[0]), "+f"(c[1]), "+f"(c[2]), "+f"(c[3])
                 : "r"(a[0]), "r"(a[1]), "r"(a[2]), "r"(a[3]), "r"(b0), "r"(b1));
}
__device__ __forceinline__ void cp_async16(uint32_t smem_dst, const void* gsrc) {
    asm volatile("cp.async.cg.shared.global [%0], [%1], 16;"
                 :: "r"(smem_dst), "l"(__cvta_generic_to_global(gsrc)) : "memory");
}
#define CP_COMMIT() asm volatile("cp.async.commit_group;" ::: "memory")
#define CP_WAIT0()  asm volatile("cp.async.wait_group 0;" ::: "memory")

__device__ __forceinline__ uint32_t cvt_h2(float lo, float hi) {
    uint32_t d;
    asm("cvt.rn.f16x2.f32 %0, %1, %2;" : "=r"(d) : "f"(hi), "f"(lo));
    return d;
}

// ---------------- pre-kernel: coalesced smem-tile transpose + fp16 ----------------
__global__ void wt_prep_kernel(const float* __restrict__ wk) {
    __shared__ float tile[32][33];
    // block: 32x8 threads; grid: (N/32, K/32) = (5, 64)
    const int nBase = blockIdx.x * 32;
    const int kBase = blockIdx.y * 32;
    const int tx = threadIdx.x, ty = threadIdx.y;
    #pragma unroll
    for (int i = 0; i < 4; ++i) {
        const int k = kBase + ty + i * 8;
        tile[ty + i * 8][tx] = wk[(size_t)k * N_DIM + nBase + tx];  // coalesced over n
    }
    __syncthreads();
    #pragma unroll
    for (int i = 0; i < 4; ++i) {
        const int n = nBase + ty + i * 8;
        g_Wt_h[(size_t)n * K_DIM + kBase + tx] = __float2half(tile[tx][ty + i * 8]); // coalesced over k
    }
}

// ---------------- main fused kernel ----------------
__global__ void __launch_bounds__(NTHREAD, 2)
caps_hmma_kernel(const float* __restrict__ inp, float* __restrict__ dout, int rows)
{
    extern __shared__ char smem[];
    const uint32_t sb = smem_u32(smem);
    const int tid  = threadIdx.x;
    const int lane = tid & 31;
    const int w    = tid >> 5;
    const int rowBase = blockIdx.x * BM;

    // 4 warps: 2 M-groups x 2 N-groups, warp tile 32x80
    const int m0 = (w >> 1) * 32;
    const int n0 = (w & 1) * 80;

    // ldmatrix per-lane offsets (bytes), row stride 144B
    const int rA = (lane & 7) + ((lane >> 3) & 1) * 8;
    const int cA = (lane >> 4) * 16;
    const int aoff = (m0 + rA) * ROWB + cA;

    const int rB = (lane & 7) + ((lane >> 4) ? 8 : 0);
    const int cB = ((lane >> 3) & 1) * 16;
    const int boff = (n0 + rB) * ROWB + cB;

    float acc[2][10][4];
    #pragma unroll
    for (int mt = 0; mt < 2; ++mt)
        #pragma unroll
        for (int j = 0; j < 10; ++j)
            #pragma unroll
            for (int e = 0; e < 4; ++e) acc[mt][j][e] = 0.0f;

    // A global-load mapping: 64 rows x 16 float4; 2 threads/row, 8 float4/thread
    const int arow  = tid >> 1;           // 0..63
    const int aseg0 = (tid & 1) * 8;      // segs aseg0..aseg0+7
    const float* aptr = inp + (size_t)(rowBase + arow) * K_DIM;

    float4 ra[8];   // A prefetch registers (held one full chunk)

    #define LDG_A(kbase)                                                      \
        do {                                                                  \
            _Pragma("unroll")                                                 \
            for (int j = 0; j < 8; ++j)                                       \
                ra[j] = *reinterpret_cast<const float4*>(                     \
                    aptr + (kbase) + (aseg0 + j) * 4);                        \
        } while (0)

    #define STS_A(st)                                                         \
        do {                                                                  \
            _Pragma("unroll")                                                 \
            for (int j = 0; j < 8; ++j) {                                     \
                uint2 hp;                                                     \
                hp.x = cvt_h2(ra[j].x, ra[j].y);                              \
                hp.y = cvt_h2(ra[j].z, ra[j].w);                              \
                *reinterpret_cast<uint2*>(smem + (st) * A_STAGE +             \
                    arow * ROWB + (aseg0 + j) * 8) = hp;                      \
            }                                                                 \
        } while (0)

    // B cp.async: 1280 16B segs, 10/thread
    #define ISSUE_B(stage_sel, kbase)                                         \
        do {                                                                  \
            const uint32_t b_dst = sb + B_BASE + (stage_sel) * B_STAGE;       \
            _Pragma("unroll")                                                 \
            for (int i = 0; i < 10; ++i) {                                    \
                const int u = tid + 128 * i;                                  \
                const int n = u >> 3, seg = u & 7;                            \
                cp_async16(b_dst + n * ROWB + seg * 16,                       \
                           g_Wt_h + (size_t)n * K_DIM + (kbase) + seg * 8);   \
            }                                                                 \
            CP_COMMIT();                                                      \
        } while (0)

    #define LOAD_FRAGS(buf, a_base, b_base, ks)                               \
        do {                                                                  \
            ldsm4(af[buf][0], (a_base) + (ks) * 32);                          \
            ldsm4(af[buf][1], (a_base) + 16 * ROWB + (ks) * 32);              \
            ldsm4(bf[buf][0], (b_base) + 0 * 16 * ROWB + (ks) * 32);          \
            ldsm4(bf[buf][1], (b_base) + 1 * 16 * ROWB + (ks) * 32);          \
            ldsm4(bf[buf][2], (b_base) + 2 * 16 * ROWB + (ks) * 32);          \
            ldsm4(bf[buf][3], (b_base) + 3 * 16 * ROWB + (ks) * 32);          \
            ldsm4(bf[buf][4], (b_base) + 4 * 16 * ROWB + (ks) * 32);          \
        } while (0)

    // ---- prologue: A(0)+B(0) into stage 0, A(1) into regs ----
    LDG_A(0);
    ISSUE_B(0, 0);
    STS_A(0);
    LDG_A(BK);
    CP_WAIT0();
    __syncthreads();

    // ---- main loop: single barrier per chunk ----
    for (int c = 0; c < NCHUNK; ++c) {
        const int s = c & 1;
        const int has_next = (c + 1) < NCHUNK;

        if (has_next) {
            STS_A(s ^ 1);                 // A(c+1): regs loaded a full chunk ago
            ISSUE_B(s ^ 1, (c + 1) * BK);
            if (c + 2 < NCHUNK)
                LDG_A((c + 2) * BK);      // A(c+2) -> regs
        }

        // ---- compute chunk c: software-pipelined K-steps, 40 MMAs each ----
        const uint32_t a_base = sb + s * A_STAGE + aoff;
        const uint32_t b_base = sb + B_BASE + s * B_STAGE + boff;

        uint32_t af[2][2][4];
        uint32_t bf[2][5][4];
        LOAD_FRAGS(0, a_base, b_base, 0);
        #pragma unroll
        for (int ks = 0; ks < 4; ++ks) {
            const int cur = ks & 1;
            if (ks < 3)
                LOAD_FRAGS(cur ^ 1, a_base, b_base, ks + 1);
            #pragma unroll
            for (int g = 0; g < 5; ++g) {
                mma16816(acc[0][2 * g],     af[cur][0], bf[cur][g][0], bf[cur][g][1]);
                mma16816(acc[1][2 * g],     af[cur][1], bf[cur][g][0], bf[cur][g][1]);
                mma16816(acc[0][2 * g + 1], af[cur][0], bf[cur][g][2], bf[cur][g][3]);
                mma16816(acc[1][2 * g + 1], af[cur][1], bf[cur][g][2], bf[cur][g][3]);
            }
        }

        if (has_next)
            CP_WAIT0();
        __syncthreads();
    }

    // ---- write C frags to padded smem hat tile ----
    float* hat = reinterpret_cast<float*>(smem);
    {
        const int cbase = n0 + (lane & 3) * 2;
        #pragma unroll
        for (int mt = 0; mt < 2; ++mt) {
            const int r0 = m0 + mt * 16 + (lane >> 2);
            #pragma unroll
            for (int j = 0; j < 10; ++j) {
                const int col = cbase + 8 * j;
                hat[r0 * HAT_STRIDE + col]           = acc[mt][j][0];
                hat[r0 * HAT_STRIDE + col + 1]       = acc[mt][j][1];
                hat[(r0 + 8) * HAT_STRIDE + col]     = acc[mt][j][2];
                hat[(r0 + 8) * HAT_STRIDE + col + 1] = acc[mt][j][3];
            }
        }
    }
    __syncthreads();

    // ---- dynamic routing: one thread per row ----
    if (tid < BM) {
        const float* h = &hat[tid * HAT_STRIDE];

        float b[NC];
        #pragma unroll
        for (int n = 0; n < NC; ++n) b[n] = 0.0f;
        float out[DC];

        #pragma unroll
        for (int it = 0; it < 3; ++it) {
            float m = b[0];
            #pragma unroll
            for (int n = 1; n < NC; ++n) m = fmaxf(m, b[n]);
            float cc[NC];
            float se = 0.0f;
            #pragma unroll
            for (int n = 0; n < NC; ++n) { cc[n] = expf(b[n] - m); se += cc[n]; }
            const float inv = 1.0f / se;

            float s[DC];
            #pragma unroll
            for (int d = 0; d < DC; ++d) s[d] = 0.0f;
            #pragma unroll
            for (int n = 0; n < NC; ++n) {
                const float cn = cc[n] * inv;
                #pragma unroll
                for (int d = 0; d < DC; ++d)
                    s[d] = fmaf(cn, h[n * DC + d], s[d]);
            }

            float s2 = 0.0f;
            #pragma unroll
            for (int d = 0; d < DC; ++d) s2 = fmaf(s[d], s[d], s2);
            const float scale = s2 / ((1.0f + s2) * sqrtf(s2 + 1e-7f));
            #pragma unroll
            for (int d = 0; d < DC; ++d) out[d] = scale * s[d];

            if (it < 2) {
                #pragma unroll
                for (int n = 0; n < NC; ++n) {
                    float dot = 0.0f;
                    #pragma unroll
                    for (int d = 0; d < DC; ++d)
                        dot = fmaf(h[n * DC + d], out[d], dot);
                    b[n] += dot;
                }
            }
        }

        float4* o = reinterpret_cast<float4*>(dout + (size_t)(rowBase + tid) * DC);
        o[0] = make_float4(out[0],  out[1],  out[2],  out[3]);
        o[1] = make_float4(out[4],  out[5],  out[6],  out[7]);
        o[2] = make_float4(out[8],  out[9],  out[10], out[11]);
        o[3] = make_float4(out[12], out[13], out[14], out[15]);
    }
}

extern "C" void kernel_launch(void* const* d_in, const int* in_sizes, int n_in,
                              void* d_out, int out_size)
{
    const float* inp = (const float*)d_in[0];
    const float* wk  = (const float*)d_in[1];
    float* out       = (float*)d_out;

    const int rows = in_sizes[0] / K_DIM;   // 16384

    dim3 pgrid(N_DIM / 32, K_DIM / 32);
    dim3 pblk(32, 8);
    wt_prep_kernel<<<pgrid, pblk>>>(wk);

    cudaFuncSetAttribute(caps_hmma_kernel,
                         cudaFuncAttributeMaxDynamicSharedMemorySize, SMEM_TOTAL);
    caps_hmma_kernel<<<rows / BM, NTHREAD, SMEM_TOTAL>>>(inp, out, rows);
}

// round 15
// speedup vs baseline: 1.1116x; 1.1116x over previous
#include <cuda_runtime.h>
#include <cuda_fp16.h>
#include <math.h>
#include <stdint.h>

#define K_DIM   2048
#define N_DIM   160
#define NC      10
#define DC      16
#define BM      128
#define BK      64
#define NCHUNK  (K_DIM / BK)          // 32
#define NTHREAD 512
#define HAT_STRIDE 165

// fp16 tiles, row stride 144B -> conflict-free ldmatrix
#define ROWB    144
#define A_STAGE (128 * ROWB)              // 18432
#define B_BASE  (2 * A_STAGE)             // 36864
#define B_STAGE (160 * ROWB)              // 23040
#define PIPE_BYTES (B_BASE + 2 * B_STAGE) // 82944
#define HAT_BYTES  (BM * HAT_STRIDE * 4)  // 84480
#define SMEM_TOTAL (HAT_BYTES > PIPE_BYTES ? HAT_BYTES : PIPE_BYTES)

// Precomputed transposed fp16 weights: Wt[n][k] = fp16(W[k][n])
__device__ __half g_Wt_h[N_DIM * K_DIM];

// ---------------- helpers ----------------
__device__ __forceinline__ uint32_t smem_u32(const void* p) {
    uint32_t a;
    asm("{ .reg .u64 t; cvta.to.shared.u64 t, %1; cvt.u32.u64 %0, t; }" : "=r"(a) : "l"(p));
    return a;
}
__device__ __forceinline__ void ldsm4(uint32_t* d, uint32_t addr) {
    asm volatile("ldmatrix.sync.aligned.m8n8.x4.shared.b16 {%0,%1,%2,%3}, [%4];"
                 : "=r"(d[0]), "=r"(d[1]), "=r"(d[2]), "=r"(d[3]) : "r"(addr));
}
__device__ __forceinline__ void ldsm2(uint32_t* d, uint32_t addr) {
    asm volatile("ldmatrix.sync.aligned.m8n8.x2.shared.b16 {%0,%1}, [%2];"
                 : "=r"(d[0]), "=r"(d[1]) : "r"(addr));
}
__device__ __forceinline__ void mma16816(float* c, const uint32_t* a,
                                         uint32_t b0, uint32_t b1) {
    asm volatile("mma.sync.aligned.m16n8k16.row.col.f32.f16.f16.f32 "
                 "{%0,%1,%2,%3}, {%4,%5,%6,%7}, {%8,%9}, {%0,%1,%2,%3};"
                 : "+f"(c[0]), "+f"(c[1]), "+f"(c[2]), "+f"(c[3])
                 : "r"(a[0]), "r"(a[1]), "r"(a[2]), "r"(a[3]), "r"(b0), "r"(b1));
}
__device__ __forceinline__ void cp_async16(uint32_t smem_dst, const void* gsrc) {
    asm volatile("cp.async.cg.shared.global [%0], [%1], 16;"
                 :: "r"(smem_dst), "l"(__cvta_generic_to_global(gsrc)) : "memory");
}
#define CP_COMMIT() asm volatile("cp.async.commit_group;" ::: "memory")
#define CP_WAIT0()  asm volatile("cp.async.wait_group 0;" ::: "memory")

__device__ __forceinline__ uint32_t cvt_h2(float lo, float hi) {
    uint32_t d;
    asm("cvt.rn.f16x2.f32 %0, %1, %2;" : "=r"(d) : "f"(hi), "f"(lo));
    return d;
}

// ---------------- pre-kernel: coalesced smem-tile transpose + fp16 ----------------
__global__ void wt_prep_kernel(const float* __restrict__ wk) {
    __shared__ float tile[32][33];
    const int nBase = blockIdx.x * 32;
    const int kBase = blockIdx.y * 32;
    const int tx = threadIdx.x, ty = threadIdx.y;
    #pragma unroll
    for (int i = 0; i < 4; ++i) {
        const int k = kBase + ty + i * 8;
        tile[ty + i * 8][tx] = wk[(size_t)k * N_DIM + nBase + tx];
    }
    __syncthreads();
    #pragma unroll
    for (int i = 0; i < 4; ++i) {
        const int n = nBase + ty + i * 8;
        g_Wt_h[(size_t)n * K_DIM + kBase + tx] = __float2half(tile[tx][ty + i * 8]);
    }
}

// ---------------- main fused kernel ----------------
__global__ void __launch_bounds__(NTHREAD, 1)
caps_hmma_kernel(const float* __restrict__ inp, float* __restrict__ dout, int rows)
{
    extern __shared__ char smem[];
    const uint32_t sb = smem_u32(smem);
    const int tid  = threadIdx.x;
    const int lane = tid & 31;
    const int w    = tid >> 5;
    const int rowBase = blockIdx.x * BM;

    // 16 warps: 4 M-groups x 4 N-groups, warp tile 32x40
    const int m0 = (w >> 2) * 32;
    const int n0 = (w & 3) * 40;

    // A ldmatrix per-lane offset (16-row block, row-major)
    const int rA = (lane & 7) + ((lane >> 3) & 1) * 8;
    const int cA = (lane >> 4) * 16;
    const int aoff = (m0 + rA) * ROWB + cA;

    // B ldsm4 per-lane offset (16 n-rows x 16 k)
    const int rB = (lane & 7) + ((lane >> 4) ? 8 : 0);
    const int cB = ((lane >> 3) & 1) * 16;
    const int boff = (n0 + rB) * ROWB + cB;
    // B ldsm2 per-lane offset (8 n-rows x 16 k), lanes 0-15 carry addresses
    const int boff2 = (n0 + 32 + (lane & 7)) * ROWB + ((lane >> 3) & 1) * 16;

    // acc[mt][j]: mt = M 16-row block (0,1); j = 8-col N frag (0..4)
    float acc[2][5][4];
    #pragma unroll
    for (int mt = 0; mt < 2; ++mt)
        #pragma unroll
        for (int j = 0; j < 5; ++j)
            #pragma unroll
            for (int e = 0; e < 4; ++e) acc[mt][j][e] = 0.0f;

    // A global-load mapping: 128 rows x 16 float4 = 2048; 4/thread
    const int arow  = tid >> 2;           // 0..127
    const int aseg0 = tid & 3;            // segs aseg0 + 4j
    const float* aptr = inp + (size_t)(rowBase + arow) * K_DIM;

    float4 ra[4];   // A prefetch registers (held one full chunk)

    #define LDG_A(kbase)                                                      \
        do {                                                                  \
            _Pragma("unroll")                                                 \
            for (int j = 0; j < 4; ++j)                                       \
                ra[j] = *reinterpret_cast<const float4*>(                     \
                    aptr + (kbase) + (aseg0 + 4 * j) * 4);                    \
        } while (0)

    #define STS_A(st)                                                         \
        do {                                                                  \
            _Pragma("unroll")                                                 \
            for (int j = 0; j < 4; ++j) {                                     \
                uint2 hp;                                                     \
                hp.x = cvt_h2(ra[j].x, ra[j].y);                              \
                hp.y = cvt_h2(ra[j].z, ra[j].w);                              \
                *reinterpret_cast<uint2*>(smem + (st) * A_STAGE +             \
                    arow * ROWB + (aseg0 + 4 * j) * 8) = hp;                  \
            }                                                                 \
        } while (0)

    // B cp.async: 1280 16B segs over 512 threads: 2 full rounds + 1 guarded
    #define ISSUE_B(stage_sel, kbase)                                         \
        do {                                                                  \
            const uint32_t b_dst = sb + B_BASE + (stage_sel) * B_STAGE;       \
            _Pragma("unroll")                                                 \
            for (int i = 0; i < 3; ++i) {                                     \
                const int u = tid + 512 * i;                                  \
                if (u < 1280) {                                               \
                    const int n = u >> 3, seg = u & 7;                        \
                    cp_async16(b_dst + n * ROWB + seg * 16,                   \
                               g_Wt_h + (size_t)n * K_DIM + (kbase) + seg * 8);\
                }                                                             \
            }                                                                 \
            CP_COMMIT();                                                      \
        } while (0)

    // frags: af[buf][mt][4], bf4a/bf4b = ldsm4 (nfrag 0-1 / 2-3), bf2 = ldsm2 (nfrag 4)
    #define LOAD_FRAGS(buf, a_base, b_base, b_base2, ks)                      \
        do {                                                                  \
            ldsm4(af[buf][0], (a_base) + (ks) * 32);                          \
            ldsm4(af[buf][1], (a_base) + 16 * ROWB + (ks) * 32);              \
            ldsm4(bf4a[buf],  (b_base) + (ks) * 32);                          \
            ldsm4(bf4b[buf],  (b_base) + 16 * ROWB + (ks) * 32);              \
            ldsm2(bf2[buf],   (b_base2) + (ks) * 32);                         \
        } while (0)

    #define DO_MMAS(buf)                                                      \
        do {                                                                  \
            mma16816(acc[0][0], af[buf][0], bf4a[buf][0], bf4a[buf][1]);      \
            mma16816(acc[1][0], af[buf][1], bf4a[buf][0], bf4a[buf][1]);      \
            mma16816(acc[0][1], af[buf][0], bf4a[buf][2], bf4a[buf][3]);      \
            mma16816(acc[1][1], af[buf][1], bf4a[buf][2], bf4a[buf][3]);      \
            mma16816(acc[0][2], af[buf][0], bf4b[buf][0], bf4b[buf][1]);      \
            mma16816(acc[1][2], af[buf][1], bf4b[buf][0], bf4b[buf][1]);      \
            mma16816(acc[0][3], af[buf][0], bf4b[buf][2], bf4b[buf][3]);      \
            mma16816(acc[1][3], af[buf][1], bf4b[buf][2], bf4b[buf][3]);      \
            mma16816(acc[0][4], af[buf][0], bf2[buf][0],  bf2[buf][1]);       \
            mma16816(acc[1][4], af[buf][1], bf2[buf][0],  bf2[buf][1]);       \
        } while (0)

    // ---- prologue: A(0)+B(0) into stage 0, A(1) into regs ----
    LDG_A(0);
    ISSUE_B(0, 0);
    STS_A(0);
    LDG_A(BK);
    CP_WAIT0();
    __syncthreads();

    // ---- main loop: single barrier per chunk ----
    for (int c = 0; c < NCHUNK; ++c) {
        const int s = c & 1;
        const int has_next = (c + 1) < NCHUNK;

        if (has_next) {
            STS_A(s ^ 1);                 // A(c+1): regs loaded one chunk ago
            ISSUE_B(s ^ 1, (c + 1) * BK);
            if (c + 2 < NCHUNK)
                LDG_A((c + 2) * BK);      // A(c+2) -> regs
        }

        // ---- compute chunk c: pipelined K-steps, 10 MMAs each ----
        const uint32_t a_base  = sb + s * A_STAGE + aoff;
        const uint32_t b_base  = sb + B_BASE + s * B_STAGE + boff;
        const uint32_t b_base2 = sb + B_BASE + s * B_STAGE + boff2;

        uint32_t af[2][2][4];
        uint32_t bf4a[2][4], bf4b[2][4], bf2[2][2];
        LOAD_FRAGS(0, a_base, b_base, b_base2, 0);
        #pragma unroll
        for (int ks = 0; ks < 4; ++ks) {
            const int cur = ks & 1;
            if (ks < 3)
                LOAD_FRAGS(cur ^ 1, a_base, b_base, b_base2, ks + 1);
            DO_MMAS(cur);
        }

        if (has_next)
            CP_WAIT0();
        __syncthreads();
    }

    // ---- write C frags to padded smem hat tile ----
    float* hat = reinterpret_cast<float*>(smem);
    {
        const int cbase = n0 + (lane & 3) * 2;
        #pragma unroll
        for (int mt = 0; mt < 2; ++mt) {
            const int r0 = m0 + mt * 16 + (lane >> 2);
            #pragma unroll
            for (int j = 0; j < 5; ++j) {
                const int col = cbase + 8 * j;
                hat[r0 * HAT_STRIDE + col]           = acc[mt][j][0];
                hat[r0 * HAT_STRIDE + col + 1]       = acc[mt][j][1];
                hat[(r0 + 8) * HAT_STRIDE + col]     = acc[mt][j][2];
                hat[(r0 + 8) * HAT_STRIDE + col + 1] = acc[mt][j][3];
            }
        }
    }
    __syncthreads();

    // ---- dynamic routing: one thread per row ----
    if (tid < BM) {
        const float* h = &hat[tid * HAT_STRIDE];

        float b[NC];
        #pragma unroll
        for (int n = 0; n < NC; ++n) b[n] = 0.0f;
        float out[DC];

        #pragma unroll
        for (int it = 0; it < 3; ++it) {
            float m = b[0];
            #pragma unroll
            for (int n = 1; n < NC; ++n) m = fmaxf(m, b[n]);
            float cc[NC];
            float se = 0.0f;
            #pragma unroll
            for (int n = 0; n < NC; ++n) { cc[n] = expf(b[n] - m); se += cc[n]; }
            const float inv = 1.0f / se;

            float s[DC];
            #pragma unroll
            for (int d = 0; d < DC; ++d) s[d] = 0.0f;
            #pragma unroll
            for (int n = 0; n < NC; ++n) {
                const float cn = cc[n] * inv;
                #pragma unroll
                for (int d = 0; d < DC; ++d)
                    s[d] = fmaf(cn, h[n * DC + d], s[d]);
            }

            float s2 = 0.0f;
            #pragma unroll
            for (int d = 0; d < DC; ++d) s2 = fmaf(s[d], s[d], s2);
            const float scale = s2 / ((1.0f + s2) * sqrtf(s2 + 1e-7f));
            #pragma unroll
            for (int d = 0; d < DC; ++d) out[d] = scale * s[d];

            if (it < 2) {
                #pragma unroll
                for (int n = 0; n < NC; ++n) {
                    float dot = 0.0f;
                    #pragma unroll
                    for (int d = 0; d < DC; ++d)
                        dot = fmaf(h[n * DC + d], out[d], dot);
                    b[n] += dot;
                }
            }
        }

        float4* o = reinterpret_cast<float4*>(dout + (size_t)(rowBase + tid) * DC);
        o[0] = make_float4(out[0],  out[1],  out[2],  out[3]);
        o[1] = make_float4(out[4],  out[5],  out[6],  out[7]);
        o[2] = make_float4(out[8],  out[9],  out[10], out[11]);
        o[3] = make_float4(out[12], out[13], out[14], out[15]);
    }
}

extern "C" void kernel_launch(void* const* d_in, const int* in_sizes, int n_in,
                              void* d_out, int out_size)
{
    const float* inp = (const float*)d_in[0];
    const float* wk  = (const float*)d_in[1];
    float* out       = (float*)d_out;

    const int rows = in_sizes[0] / K_DIM;   // 16384

    dim3 pgrid(N_DIM / 32, K_DIM / 32);
    dim3 pblk(32, 8);
    wt_prep_kernel<<<pgrid, pblk>>>(wk);

    cudaFuncSetAttribute(caps_hmma_kernel,
                         cudaFuncAttributeMaxDynamicSharedMemorySize, SMEM_TOTAL);
    caps_hmma_kernel<<<rows / BM, NTHREAD, SMEM_TOTAL>>>(inp, out, rows);
}